// round 16
// baseline (speedup 1.0000x reference)
#include <cuda_runtime.h>

#define FULLMASK 0xffffffffu

// ---------------- scratch (device globals; no allocations allowed) ----------
__device__ float g_cyc[1024 * 8];
__device__ float g_q[1024 * 8];
__device__ float g_k[1024 * 8];
__device__ float g_v[1024 * 8];
__device__ float g_coll[1024 * 8];
__device__ float g_lg[1024];
__device__ int   g_cnt = 0;

__device__ __forceinline__ float safef(float x) {
    return fminf(fmaxf(x, -10000.f), 10000.f);
}
__device__ __forceinline__ float dot4(float4 a, float4 b) {
    return a.x * b.x + a.y * b.y + a.z * b.z + a.w * b.w;
}
__device__ __forceinline__ unsigned long long pack2(float lo, float hi) {
    unsigned long long r;
    asm("mov.b64 %0, {%1, %2};" : "=l"(r) : "f"(lo), "f"(hi));
    return r;
}
__device__ __forceinline__ void unpack2(unsigned long long v, float& lo, float& hi) {
    asm("mov.b64 {%0, %1}, %2;" : "=f"(lo), "=f"(hi) : "l"(v));
}
__device__ __forceinline__ unsigned long long fma2(unsigned long long a, unsigned long long b, unsigned long long c) {
    unsigned long long d;
    asm("fma.rn.f32x2 %0, %1, %2, %3;" : "=l"(d) : "l"(a), "l"(b), "l"(c));
    return d;
}
__device__ __forceinline__ float warp_sum(float v) {
    #pragma unroll
    for (int off = 16; off; off >>= 1) v += __shfl_xor_sync(FULLMASK, v, off);
    return v;
}

// =====================================================================
// K1: per-cycle pipeline, TWO cycles per block (unchanged from R15).
// =====================================================================
__global__ void __launch_bounds__(256) cycle_kernel(
    const float* __restrict__ df,
    const float* __restrict__ de_w, const float* __restrict__ de_b,
    const float* __restrict__ ca_in_w, const float* __restrict__ ca_in_b,
    const float* __restrict__ ca_out_w, const float* __restrict__ ca_out_b,
    const float* __restrict__ cn_g, const float* __restrict__ cn_b,
    const float* __restrict__ cs_w, const float* __restrict__ cs_b,
    const float* __restrict__ cp_ln_g, const float* __restrict__ cp_ln_b,
    const float* __restrict__ cp_w1, const float* __restrict__ cp_b1,
    const float* __restrict__ cp_w2, const float* __restrict__ cp_b2,
    const float* __restrict__ ia_in_w, const float* __restrict__ ia_in_b)
{
    __shared__ float sdxA[256], sdyA[256], sdxB[256], sdyB[256];
    __shared__ float sktA[16 * 256], sktB[16 * 256];
    __shared__ __align__(16) float sW[736];
    __shared__ __align__(16) unsigned long long sQw2[96];
    __shared__ __align__(16) unsigned long long sOw2[32];
    __shared__ unsigned long long sQb2[12];
    __shared__ float redx[2][8], redy[2][8], wred[2][8], sumw[2][8], spool[2][8];

    int tid = threadIdx.x;
    int lane = tid & 31, warp = tid >> 5;
    int c0 = blockIdx.x * 2;

    if (tid < 192) sW[512 + tid] = ia_in_w[tid];
    if (tid < 96) {
        int p = tid >> 3, k = tid & 7;
        sQw2[tid] = pack2(ca_in_w[2 * p * 8 + k], ca_in_w[(2 * p + 1) * 8 + k]);
    } else if (tid < 128) {
        int i = tid - 96, p = i >> 3, k = i & 7;
        sOw2[i] = pack2(ca_out_w[2 * p * 8 + k], ca_out_w[(2 * p + 1) * 8 + k]);
    } else if (tid < 140) {
        int i = tid - 128;
        sQb2[i] = pack2(ca_in_b[2 * i], ca_in_b[2 * i + 1]);
    }
    if (tid >= 140 && tid < 164) sW[288 + (tid - 140)] = de_w[tid - 140];
    if (tid >= 164 && tid < 188) sW[704 + (tid - 164)] = ia_in_b[tid - 164];
    if (tid >= 192 && tid < 256) {
        int i = tid - 192;
        sW[368 + i] = cp_w1[i];
        sW[440 + i] = cp_w2[i];
    }
    if (tid < 8) {
        sW[280 + tid] = ca_out_b[tid];
        sW[312 + tid] = de_b[tid];
        sW[320 + tid] = cn_g[tid];
        sW[328 + tid] = cn_b[tid];
        sW[336 + tid] = cs_w[tid];
        sW[352 + tid] = cp_ln_g[tid];
        sW[360 + tid] = cp_ln_b[tid];
        sW[432 + tid] = cp_b1[tid];
        sW[504 + tid] = cp_b2[tid];
    }
    if (tid == 8) sW[344] = cs_b[0];

    const float* bA = df + (size_t)c0 * 768;
    const float* bB = bA + 768;
    float dxA = bA[3 * tid], dyA = bA[3 * tid + 1];
    float dxB = bB[3 * tid], dyB = bB[3 * tid + 1];
    sdxA[tid] = dxA; sdyA[tid] = dyA;
    sdxB[tid] = dxB; sdyB[tid] = dyB;

    float sxA = dxA, syA = dyA, sxB = dxB, syB = dyB;
    #pragma unroll
    for (int off = 1; off < 32; off <<= 1) {
        float t0 = __shfl_up_sync(FULLMASK, sxA, off);
        float t1 = __shfl_up_sync(FULLMASK, syA, off);
        float t2 = __shfl_up_sync(FULLMASK, sxB, off);
        float t3 = __shfl_up_sync(FULLMASK, syB, off);
        if (lane >= off) { sxA += t0; syA += t1; sxB += t2; syB += t3; }
    }
    if (lane == 31) {
        redx[0][warp] = sxA; redy[0][warp] = syA;
        redx[1][warp] = sxB; redy[1][warp] = syB;
    }
    __syncthreads();                                       // (1)
    float bxA = 0.f, byA = 0.f, bxB = 0.f, byB = 0.f;
    #pragma unroll
    for (int w = 0; w < 8; ++w) {
        if (w < warp) {
            bxA += redx[0][w]; byA += redy[0][w];
            bxB += redx[1][w]; byB += redy[1][w];
        }
    }
    float VxA = bxA + sxA - dxA, VyA = byA + syA - dyA;
    float VxB = bxB + sxB - dxB, VyB = byB + syB - dyB;
    float crA = (tid < 255) ? (VxA * dyA - VyA * dxA) : 0.f;
    float crB = (tid < 255) ? (VxB * dyB - VyB * dxB) : 0.f;
    crA = warp_sum(crA);
    crB = warp_sum(crB);
    if (lane == 0) { wred[0][warp] = crA; wred[1][warp] = crB; }
    __syncthreads();                                       // (2)
    float areaA = 0.f, areaB = 0.f;
    #pragma unroll
    for (int w = 0; w < 8; ++w) { areaA += wred[0][w]; areaB += wred[1][w]; }
    bool flipA = areaA < 0.f, flipB = areaB < 0.f;

    float exA = flipA ? -sdxA[255 - tid] : dxA;
    float eyA = flipA ? -sdyA[255 - tid] : dyA;
    float exB = flipB ? -sdxB[255 - tid] : dxB;
    float eyB = flipB ? -sdyB[255 - tid] : dyB;
    float fnA = safef(sqrtf(exA * exA + eyA * eyA));
    float fnB = safef(sqrtf(exB * exB + eyB * eyB));
    float fxA = safef(exA), fyA = safef(eyA);
    float fxB = safef(exB), fyB = safef(eyB);

    float embA[8], embB[8];
    #pragma unroll
    for (int j = 0; j < 8; ++j) {
        float w0 = sW[288 + 3 * j], w1 = sW[288 + 3 * j + 1], w2 = sW[288 + 3 * j + 2];
        float bb = sW[312 + j];
        embA[j] = safef(fmaxf(fxA * w0 + fyA * w1 + fnA * w2 + bb, 0.f));
        embB[j] = safef(fmaxf(fxB * w0 + fyB * w1 + fnB * w2 + bb, 0.f));
    }

    unsigned long long eA2[8], eB2[8];
    #pragma unroll
    for (int k = 0; k < 8; ++k) {
        eA2[k] = pack2(embA[k], embA[k]);
        eB2[k] = pack2(embB[k], embB[k]);
    }
    float qvA[8], kregA[8], vregA[8], qvB[8], kregB[8], vregB[8];
    #pragma unroll
    for (int p = 0; p < 4; ++p) {
        unsigned long long bb = sQb2[p];
        unsigned long long aA = bb, aB = bb;
        #pragma unroll
        for (int k = 0; k < 8; ++k) {
            unsigned long long w = sQw2[p * 8 + k];
            aA = fma2(eA2[k], w, aA);
            aB = fma2(eB2[k], w, aB);
        }
        unpack2(aA, qvA[2 * p], qvA[2 * p + 1]);
        unpack2(aB, qvB[2 * p], qvB[2 * p + 1]);
    }
    #pragma unroll
    for (int p = 0; p < 4; ++p) {
        unsigned long long bb = sQb2[4 + p];
        unsigned long long aA = bb, aB = bb;
        #pragma unroll
        for (int k = 0; k < 8; ++k) {
            unsigned long long w = sQw2[(4 + p) * 8 + k];
            aA = fma2(eA2[k], w, aA);
            aB = fma2(eB2[k], w, aB);
        }
        unpack2(aA, kregA[2 * p], kregA[2 * p + 1]);
        unpack2(aB, kregB[2 * p], kregB[2 * p + 1]);
    }
    #pragma unroll
    for (int p = 0; p < 4; ++p) {
        unsigned long long bb = sQb2[8 + p];
        unsigned long long aA = bb, aB = bb;
        #pragma unroll
        for (int k = 0; k < 8; ++k) {
            unsigned long long w = sQw2[(8 + p) * 8 + k];
            aA = fma2(eA2[k], w, aA);
            aB = fma2(eB2[k], w, aB);
        }
        unpack2(aA, vregA[2 * p], vregA[2 * p + 1]);
        unpack2(aB, vregB[2 * p], vregB[2 * p + 1]);
    }
    #pragma unroll
    for (int j = 0; j < 8; ++j) {
        sktA[j * 256 + tid] = kregA[j];
        sktA[(8 + j) * 256 + tid] = vregA[j];
        sktB[j * 256 + tid] = kregB[j];
        sktB[(8 + j) * 256 + tid] = vregB[j];
    }
    __syncthreads();                                       // (3)

    int im = (tid + 255) & 255, ip = (tid + 1) & 255;
    float oA[8], oB[8];
#define ATTN3(skt, kreg, vreg, qv, o)                                          \
    {                                                                          \
        float km[8], kp[8], vm[8], vp[8];                                      \
        _Pragma("unroll")                                                      \
        for (int j = 0; j < 8; ++j) {                                          \
            km[j] = skt[j * 256 + im];                                         \
            kp[j] = skt[j * 256 + ip];                                         \
            vm[j] = skt[(8 + j) * 256 + im];                                   \
            vp[j] = skt[(8 + j) * 256 + ip];                                   \
        }                                                                      \
        _Pragma("unroll")                                                      \
        for (int h = 0; h < 2; ++h) {                                          \
            int b4 = h * 4;                                                    \
            float s0 = 0.f, s1 = 0.f, s2 = 0.f;                                \
            _Pragma("unroll")                                                  \
            for (int j = 0; j < 4; ++j) {                                      \
                s0 += qv[b4 + j] * km[b4 + j];                                 \
                s1 += qv[b4 + j] * kreg[b4 + j];                               \
                s2 += qv[b4 + j] * kp[b4 + j];                                 \
            }                                                                  \
            s0 *= 0.5f; s1 *= 0.5f; s2 *= 0.5f;                                \
            float mm = fmaxf(s0, fmaxf(s1, s2));                               \
            float p0 = __expf(s0 - mm), p1 = __expf(s1 - mm), p2 = __expf(s2 - mm); \
            float inv = 1.f / (p0 + p1 + p2);                                  \
            _Pragma("unroll")                                                  \
            for (int j = 0; j < 4; ++j)                                        \
                o[b4 + j] = (p0 * vm[b4 + j] + p1 * vreg[b4 + j] + p2 * vp[b4 + j]) * inv; \
        }                                                                      \
    }
    ATTN3(sktA, kregA, vregA, qvA, oA)
    ATTN3(sktB, kregB, vregB, qvB, oB)
#undef ATTN3

    unsigned long long oA2[8], oB2[8];
    #pragma unroll
    for (int k = 0; k < 8; ++k) {
        oA2[k] = pack2(oA[k], oA[k]);
        oB2[k] = pack2(oB[k], oB[k]);
    }
    float xA[8], xB[8];
    float muA = 0.f, muB = 0.f;
    #pragma unroll
    for (int p = 0; p < 4; ++p) {
        unsigned long long bb = pack2(sW[280 + 2 * p], sW[280 + 2 * p + 1]);
        unsigned long long aA = bb, aB = bb;
        #pragma unroll
        for (int k = 0; k < 8; ++k) {
            unsigned long long w = sOw2[p * 8 + k];
            aA = fma2(oA2[k], w, aA);
            aB = fma2(oB2[k], w, aB);
        }
        float lo, hi;
        unpack2(aA, lo, hi);
        xA[2 * p]     = safef(embA[2 * p] + lo);
        xA[2 * p + 1] = safef(embA[2 * p + 1] + hi);
        muA += xA[2 * p] + xA[2 * p + 1];
        unpack2(aB, lo, hi);
        xB[2 * p]     = safef(embB[2 * p] + lo);
        xB[2 * p + 1] = safef(embB[2 * p + 1] + hi);
        muB += xB[2 * p] + xB[2 * p + 1];
    }
    muA *= 0.125f; muB *= 0.125f;
    float varA = 0.f, varB = 0.f;
    #pragma unroll
    for (int j = 0; j < 8; ++j) {
        float dA = xA[j] - muA; varA += dA * dA;
        float dB = xB[j] - muB; varB += dB * dB;
    }
    float rsA = rsqrtf(varA * 0.125f + 1e-5f);
    float rsB = rsqrtf(varB * 0.125f + 1e-5f);
    float e2A[8], e2B[8];
    float lgA = sW[344], lgB = sW[344];
    #pragma unroll
    for (int j = 0; j < 8; ++j) {
        float gg = sW[320 + j], bb2 = sW[328 + j], sw = sW[336 + j];
        e2A[j] = safef((xA[j] - muA) * rsA * gg + bb2);
        e2B[j] = safef((xB[j] - muB) * rsB * gg + bb2);
        lgA += e2A[j] * sw;
        lgB += e2B[j] * sw;
    }
    lgA = safef(lgA); lgB = safef(lgB);

    float evA = __expf(lgA), evB = __expf(lgB);
    float svA = warp_sum(evA), svB = warp_sum(evB);
    if (lane == 0) { sumw[0][warp] = svA; sumw[1][warp] = svB; }
    __syncthreads();                                       // (4)
    float SA = 0.f, SB = 0.f;
    #pragma unroll
    for (int w = 0; w < 8; ++w) { SA += sumw[0][w]; SB += sumw[1][w]; }
    float wgtA = evA / SA, wgtB = evB / SB;

    #pragma unroll
    for (int j = 0; j < 8; ++j) {
        sktA[j * 256 + tid] = wgtA * e2A[j];
        sktB[j * 256 + tid] = wgtB * e2B[j];
    }
    __syncthreads();                                       // (5)
    {
        float aA = 0.f, aB = 0.f;
        #pragma unroll
        for (int i = 0; i < 8; ++i) {
            aA += sktA[warp * 256 + i * 32 + lane];
            aB += sktB[warp * 256 + i * 32 + lane];
        }
        aA = warp_sum(aA);
        aB = warp_sum(aB);
        if (lane == 0) { spool[0][warp] = aA; spool[1][warp] = aB; }
    }
    __syncthreads();                                       // (6)

    if (warp < 2) {
        int cc = warp;
        int c = c0 + cc;
        float p[8];
        #pragma unroll
        for (int j = 0; j < 8; ++j) p[j] = spool[cc][j];
        float pm = 0.f;
        #pragma unroll
        for (int j = 0; j < 8; ++j) pm += p[j];
        pm *= 0.125f;
        float pv = 0.f;
        #pragma unroll
        for (int j = 0; j < 8; ++j) { float d = p[j] - pm; pv += d * d; }
        pv *= 0.125f;
        float prs = rsqrtf(pv + 1e-5f);
        float h[8];
        #pragma unroll
        for (int j = 0; j < 8; ++j)
            h[j] = (p[j] - pm) * prs * sW[352 + j] + sW[360 + j];
        float h1[8];
        #pragma unroll
        for (int j = 0; j < 8; ++j) {
            float s = sW[432 + j];
            #pragma unroll
            for (int k = 0; k < 8; ++k) s += h[k] * sW[368 + j * 8 + k];
            h1[j] = fmaxf(s, 0.f);
        }
        float cy[8];
        #pragma unroll
        for (int j = 0; j < 8; ++j) {
            float s = sW[504 + j];
            #pragma unroll
            for (int k = 0; k < 8; ++k) s += h1[k] * sW[440 + j * 8 + k];
            cy[j] = safef(s);
        }
        if (lane < 8) g_cyc[c * 8 + lane] = cy[lane];
        if (lane < 24) {
            float s = sW[704 + lane];
            #pragma unroll
            for (int k = 0; k < 8; ++k) s += cy[k] * sW[512 + lane * 8 + k];
            int j = lane & 7;
            if (lane < 8)       g_q[c * 8 + j] = s;
            else if (lane < 16) g_k[c * 8 + j] = s;
            else                g_v[c * 8 + j] = s;
        }
    }
}

// =====================================================================
// K2 (+ fused final): direct-LDG attention (no smem staging; K/V fits
// in L1). 128 blocks x 512 thr: warp = (qgroup of 4, chunk of 128 keys).
// =====================================================================
__global__ void __launch_bounds__(512) coll_attn_kernel(
    const float* __restrict__ ia_out_w, const float* __restrict__ ia_out_b,
    const float* __restrict__ in_g, const float* __restrict__ in_b,
    const float* __restrict__ is_w, const float* __restrict__ is_b,
    const float* __restrict__ tp_ln_g, const float* __restrict__ tp_ln_b,
    const float* __restrict__ tp_w1, const float* __restrict__ tp_b1,
    const float* __restrict__ tp_w2, const float* __restrict__ tp_b2,
    float* __restrict__ out)
{
    __shared__ float spart[8 * 8 * 10];
    __shared__ float smrg[8 * 10];
    __shared__ float sWK2[264];
    __shared__ float red2[16], fp[16 * 8];
    __shared__ int s_last;

    int tid = threadIdx.x, lane = tid & 31, warp = tid >> 5;
    int g = warp >> 3;
    int ch = warp & 7;
    int qbase = blockIdx.x * 8 + g * 4;

    const float4* gq = (const float4*)g_q;
    const float4* gk = (const float4*)g_k;
    const float4* gv = (const float4*)g_v;

    // ---- stage small weights into smem
    if (tid < 64) {
        sWK2[tid]       = ia_out_w[tid];
        sWK2[120 + tid] = tp_w1[tid];
        sWK2[192 + tid] = tp_w2[tid];
    } else if (tid < 72) {
        int i = tid - 64;
        sWK2[64 + i]  = ia_out_b[i];
        sWK2[72 + i]  = in_g[i];
        sWK2[80 + i]  = in_b[i];
        sWK2[88 + i]  = is_w[i];
        sWK2[104 + i] = tp_ln_g[i];
        sWK2[112 + i] = tp_ln_b[i];
        sWK2[184 + i] = tp_b1[i];
        sWK2[256 + i] = tp_b2[i];
    } else if (tid == 72) {
        sWK2[96] = is_b[0];
    }

    float4 q0[4], q1[4];
    #pragma unroll
    for (int qq = 0; qq < 4; ++qq) {
        float4 a = __ldg(gq + (qbase + qq) * 2), b = __ldg(gq + (qbase + qq) * 2 + 1);
        a.x *= 0.5f; a.y *= 0.5f; a.z *= 0.5f; a.w *= 0.5f;
        b.x *= 0.5f; b.y *= 0.5f; b.z *= 0.5f; b.w *= 0.5f;
        q0[qq] = a; q1[qq] = b;
    }

    int kb = ch * 128;

    // ---- single pass: direct exp + accumulate, K/V via LDG (L1-hot)
    float l[8] = {0, 0, 0, 0, 0, 0, 0, 0};
    float4 acc[8];
    #pragma unroll
    for (int j = 0; j < 8; ++j) acc[j] = make_float4(0, 0, 0, 0);
    #pragma unroll
    for (int it = 0; it < 4; ++it) {
        int t = kb + it * 32 + lane;
        float4 k0 = __ldg(gk + t * 2), k1 = __ldg(gk + t * 2 + 1);
        float4 v0 = __ldg(gv + t * 2), v1 = __ldg(gv + t * 2 + 1);
        #pragma unroll
        for (int qq = 0; qq < 4; ++qq) {
            float p0 = __expf(dot4(q0[qq], k0));
            float p1 = __expf(dot4(q1[qq], k1));
            l[2 * qq] += p0; l[2 * qq + 1] += p1;
            acc[2 * qq].x += p0 * v0.x; acc[2 * qq].y += p0 * v0.y;
            acc[2 * qq].z += p0 * v0.z; acc[2 * qq].w += p0 * v0.w;
            acc[2 * qq + 1].x += p1 * v1.x; acc[2 * qq + 1].y += p1 * v1.y;
            acc[2 * qq + 1].z += p1 * v1.z; acc[2 * qq + 1].w += p1 * v1.w;
        }
    }

    #pragma unroll
    for (int j = 0; j < 8; ++j) {
        l[j]     = warp_sum(l[j]);
        acc[j].x = warp_sum(acc[j].x);
        acc[j].y = warp_sum(acc[j].y);
        acc[j].z = warp_sum(acc[j].z);
        acc[j].w = warp_sum(acc[j].w);
    }

    #pragma unroll
    for (int qq = 0; qq < 4; ++qq) {
        if (lane == qq) {
            float* pr = &spart[((g * 4 + qq) * 8 + ch) * 10];
            pr[0] = l[2 * qq];
            pr[1] = acc[2 * qq].x;   pr[2] = acc[2 * qq].y;
            pr[3] = acc[2 * qq].z;   pr[4] = acc[2 * qq].w;
            pr[5] = l[2 * qq + 1];
            pr[6] = acc[2 * qq + 1].x; pr[7] = acc[2 * qq + 1].y;
            pr[8] = acc[2 * qq + 1].z; pr[9] = acc[2 * qq + 1].w;
        }
    }
    __syncthreads();

    // ---- merge: warp per query (warps 0-7)
    if (warp < 8) {
        int q = blockIdx.x * 8 + warp;
        if (lane < 10) {
            const float* pb = &spart[warp * 80];
            float s = 0.f;
            #pragma unroll
            for (int cc = 0; cc < 8; ++cc) s += pb[cc * 10 + lane];
            smrg[warp * 10 + lane] = s;
        }
        __syncwarp();
        const float* mg = &smrg[warp * 10];
        float inv0 = 1.f / mg[0];
        float inv1 = 1.f / mg[5];
        int j = lane & 7;
        float s = sWK2[64 + j];
        #pragma unroll
        for (int k = 0; k < 4; ++k) s += (mg[1 + k] * inv0) * sWK2[j * 8 + k];
        #pragma unroll
        for (int k = 0; k < 4; ++k) s += (mg[6 + k] * inv1) * sWK2[j * 8 + 4 + k];
        float x = safef(g_cyc[q * 8 + j] + s);
        float mu = x;
        mu += __shfl_xor_sync(FULLMASK, mu, 1);
        mu += __shfl_xor_sync(FULLMASK, mu, 2);
        mu += __shfl_xor_sync(FULLMASK, mu, 4);
        mu *= 0.125f;
        float d = x - mu;
        float var = d * d;
        var += __shfl_xor_sync(FULLMASK, var, 1);
        var += __shfl_xor_sync(FULLMASK, var, 2);
        var += __shfl_xor_sync(FULLMASK, var, 4);
        var *= 0.125f;
        float rs = rsqrtf(var + 1e-5f);
        float cj = safef(d * rs * sWK2[72 + j] + sWK2[80 + j]);
        float lt = cj * sWK2[88 + j];
        lt += __shfl_xor_sync(FULLMASK, lt, 1);
        lt += __shfl_xor_sync(FULLMASK, lt, 2);
        lt += __shfl_xor_sync(FULLMASK, lt, 4);
        if (lane < 8) g_coll[q * 8 + lane] = cj;
        if (lane == 0) g_lg[q] = safef(lt + sWK2[96]);
    }

    // ---- last-block-done handoff -> fused final stage
    __syncthreads();
    if (tid == 0) {
        __threadfence();
        int old = atomicAdd(&g_cnt, 1);
        s_last = (old == (int)gridDim.x - 1) ? 1 : 0;
    }
    __syncthreads();
    if (!s_last) return;

    if (tid == 0) g_cnt = 0;
    __threadfence();

    float lga = g_lg[tid], lgb = g_lg[tid + 512];
    float ea = __expf(lga), eb = __expf(lgb);
    float sve = warp_sum(ea + eb);
    if (lane == 0) red2[warp] = sve;

    const float4* gc = (const float4*)g_coll;
    float4 c0 = gc[tid * 2], c1 = gc[tid * 2 + 1];
    float4 d0 = gc[(tid + 512) * 2], d1 = gc[(tid + 512) * 2 + 1];
    float pacc[8] = { ea * c0.x + eb * d0.x, ea * c0.y + eb * d0.y,
                      ea * c0.z + eb * d0.z, ea * c0.w + eb * d0.w,
                      ea * c1.x + eb * d1.x, ea * c1.y + eb * d1.y,
                      ea * c1.z + eb * d1.z, ea * c1.w + eb * d1.w };
    #pragma unroll
    for (int j = 0; j < 8; ++j) {
        float v = pacc[j];
        #pragma unroll
        for (int off = 16; off; off >>= 1) v += __shfl_down_sync(FULLMASK, v, off);
        if (lane == 0) fp[warp * 8 + j] = v;
    }
    __syncthreads();
    if (tid == 0) {
        float S = 0.f;
        #pragma unroll
        for (int w = 0; w < 16; ++w) S += red2[w];
        float invS = 1.f / S;
        float p[8];
        #pragma unroll
        for (int j = 0; j < 8; ++j) {
            float a = 0.f;
            #pragma unroll
            for (int w = 0; w < 16; ++w) a += fp[w * 8 + j];
            p[j] = a * invS;
        }
        float pm = 0.f;
        #pragma unroll
        for (int j = 0; j < 8; ++j) pm += p[j];
        pm *= 0.125f;
        float pvv = 0.f;
        #pragma unroll
        for (int j = 0; j < 8; ++j) { float d = p[j] - pm; pvv += d * d; }
        pvv *= 0.125f;
        float prs = rsqrtf(pvv + 1e-5f);
        float h[8];
        #pragma unroll
        for (int j = 0; j < 8; ++j)
            h[j] = (p[j] - pm) * prs * sWK2[104 + j] + sWK2[112 + j];
        float h1[8];
        #pragma unroll
        for (int j = 0; j < 8; ++j) {
            float a = sWK2[184 + j];
            #pragma unroll
            for (int k = 0; k < 8; ++k) a += h[k] * sWK2[120 + j * 8 + k];
            h1[j] = fmaxf(a, 0.f);
        }
        #pragma unroll
        for (int j = 0; j < 8; ++j) {
            float a = sWK2[256 + j];
            #pragma unroll
            for (int k = 0; k < 8; ++k) a += h1[k] * sWK2[192 + j * 8 + k];
            out[j] = safef(a);
        }
    }
}

// =====================================================================
extern "C" void kernel_launch(void* const* d_in, const int* in_sizes, int n_in,
                              void* d_out, int out_size) {
    const float* df      = (const float*)d_in[0];
    const float* de_w    = (const float*)d_in[1];
    const float* de_b    = (const float*)d_in[2];
    const float* ca_in_w = (const float*)d_in[3];
    const float* ca_in_b = (const float*)d_in[4];
    const float* ca_out_w= (const float*)d_in[5];
    const float* ca_out_b= (const float*)d_in[6];
    const float* cn_g    = (const float*)d_in[7];
    const float* cn_b    = (const float*)d_in[8];
    const float* cs_w    = (const float*)d_in[9];
    const float* cs_b    = (const float*)d_in[10];
    const float* cp_ln_g = (const float*)d_in[11];
    const float* cp_ln_b = (const float*)d_in[12];
    const float* cp_w1   = (const float*)d_in[13];
    const float* cp_b1   = (const float*)d_in[14];
    const float* cp_w2   = (const float*)d_in[15];
    const float* cp_b2   = (const float*)d_in[16];
    const float* ia_in_w = (const float*)d_in[17];
    const float* ia_in_b = (const float*)d_in[18];
    const float* ia_out_w= (const float*)d_in[19];
    const float* ia_out_b= (const float*)d_in[20];
    const float* in_g    = (const float*)d_in[21];
    const float* in_b    = (const float*)d_in[22];
    const float* is_w    = (const float*)d_in[23];
    const float* is_b    = (const float*)d_in[24];
    const float* tp_ln_g = (const float*)d_in[25];
    const float* tp_ln_b = (const float*)d_in[26];
    const float* tp_w1   = (const float*)d_in[27];
    const float* tp_b1   = (const float*)d_in[28];
    const float* tp_w2   = (const float*)d_in[29];
    const float* tp_b2   = (const float*)d_in[30];

    cycle_kernel<<<512, 256>>>(df, de_w, de_b, ca_in_w, ca_in_b, ca_out_w, ca_out_b,
                               cn_g, cn_b, cs_w, cs_b, cp_ln_g, cp_ln_b,
                               cp_w1, cp_b1, cp_w2, cp_b2, ia_in_w, ia_in_b);
    coll_attn_kernel<<<128, 512>>>(ia_out_w, ia_out_b, in_g, in_b, is_w, is_b,
                                   tp_ln_g, tp_ln_b, tp_w1, tp_b1, tp_w2, tp_b2,
                                   (float*)d_out);
}